// round 1
// baseline (speedup 1.0000x reference)
#include <cuda_runtime.h>
#include <math.h>
#include <stdint.h>

// ---------------- problem constants ----------------
#define NTOK   2048      // B*S tokens
#define NEXP   64        // routed experts
#define TOPK   6
#define CAP    512       // per-expert capacity
#define HDIM   2048      // hidden
#define IDIM   768       // moe intermediate
#define TWOI   1536      // 2*I
#define SIDIM  1536      // shared experts intermediate

// ---------------- GEMM tile config ----------------
#define BM 64
#define BN 64
#define BK 16
#define NTH 128          // 4 warps, 2x2 warp grid, 32x32 per warp

// ---------------- scratch (device globals: no allocations allowed) ----------------
__device__ int   g_counts[NEXP];
__device__ int   g_buf_tok[NEXP * CAP];
__device__ float g_buf_w[NEXP * CAP];
__device__ float g_logits[NTOK * NEXP];
__device__ float g_hid[(size_t)NEXP * CAP * IDIM];   // ~96 MB
__device__ float g_shid[(size_t)NTOK * SIDIM];       // ~12.6 MB

// ---------------- helpers ----------------
__device__ __forceinline__ unsigned f2tf(float x) {
    unsigned y;
    asm("cvt.rna.tf32.f32 %0, %1;" : "=r"(y) : "f"(x));
    return y;
}

__device__ __forceinline__ void mma8(float c[4], const unsigned a[4], const unsigned b[2]) {
    asm volatile(
        "mma.sync.aligned.m16n8k8.row.col.f32.tf32.tf32.f32 "
        "{%0,%1,%2,%3}, {%4,%5,%6,%7}, {%8,%9}, {%0,%1,%2,%3};"
        : "+f"(c[0]), "+f"(c[1]), "+f"(c[2]), "+f"(c[3])
        : "r"(a[0]), "r"(a[1]), "r"(a[2]), "r"(a[3]), "r"(b[0]), "r"(b[1]));
}

__device__ __forceinline__ float silu_f(float v) { return v / (1.0f + expf(-v)); }

// Warp-level 64x64 tile MAC over one BK slab.
// As[k][m], Bs[k][n]. PRECISE=1 uses 3xTF32 (hi/lo split) for ~fp32 accuracy.
template<int PRECISE>
__device__ __forceinline__ void mma_tile(const float (*As)[BM + 4], const float (*Bs)[BN + 4],
                                         float acc[2][4][4], int wm, int wn, int gq, int tq) {
#pragma unroll
    for (int kk = 0; kk < BK; kk += 8) {
        float af[2][4], bf[4][2];
#pragma unroll
        for (int mt = 0; mt < 2; mt++) {
            int rb = wm * 32 + mt * 16;
            af[mt][0] = As[kk + tq    ][rb + gq    ];
            af[mt][1] = As[kk + tq    ][rb + gq + 8];
            af[mt][2] = As[kk + tq + 4][rb + gq    ];
            af[mt][3] = As[kk + tq + 4][rb + gq + 8];
        }
#pragma unroll
        for (int nt = 0; nt < 4; nt++) {
            int cb = wn * 32 + nt * 8 + gq;
            bf[nt][0] = Bs[kk + tq    ][cb];
            bf[nt][1] = Bs[kk + tq + 4][cb];
        }
        unsigned ah[2][4], bh[4][2];
#pragma unroll
        for (int mt = 0; mt < 2; mt++)
#pragma unroll
            for (int i = 0; i < 4; i++) ah[mt][i] = f2tf(af[mt][i]);
#pragma unroll
        for (int nt = 0; nt < 4; nt++)
#pragma unroll
            for (int i = 0; i < 2; i++) bh[nt][i] = f2tf(bf[nt][i]);

        if (PRECISE) {
            unsigned al[2][4], bl[4][2];
#pragma unroll
            for (int mt = 0; mt < 2; mt++)
#pragma unroll
                for (int i = 0; i < 4; i++)
                    al[mt][i] = f2tf(af[mt][i] - __uint_as_float(ah[mt][i]));
#pragma unroll
            for (int nt = 0; nt < 4; nt++)
#pragma unroll
                for (int i = 0; i < 2; i++)
                    bl[nt][i] = f2tf(bf[nt][i] - __uint_as_float(bh[nt][i]));
#pragma unroll
            for (int mt = 0; mt < 2; mt++)
#pragma unroll
                for (int nt = 0; nt < 4; nt++) {
                    mma8(acc[mt][nt], al[mt], bh[nt]);
                    mma8(acc[mt][nt], ah[mt], bl[nt]);
                    mma8(acc[mt][nt], ah[mt], bh[nt]);
                }
        } else {
#pragma unroll
            for (int mt = 0; mt < 2; mt++)
#pragma unroll
                for (int nt = 0; nt < 4; nt++)
                    mma8(acc[mt][nt], ah[mt], bh[nt]);
        }
    }
}

// Load a 64(row) x 16(k) tile from row-major src (row stride ld), transposed into S[k][row].
// src must point at (row0, k=0); k0 selects the k slab. Used for A and for [N,K]-layout B.
__device__ __forceinline__ void load_t64(float (*S)[BM + 4], const float* __restrict__ src,
                                         int ld, int k0, int tid) {
#pragma unroll
    for (int j = 0; j < 2; j++) {
        int it = tid + j * NTH;
        int r = it >> 2, c4 = it & 3;
        float4 v = *(const float4*)(src + (size_t)r * ld + k0 + c4 * 4);
        S[c4 * 4 + 0][r] = v.x;
        S[c4 * 4 + 1][r] = v.y;
        S[c4 * 4 + 2][r] = v.z;
        S[c4 * 4 + 3][r] = v.w;
    }
}

// Gathered variant: row r comes from token s_tok[r] of x.
__device__ __forceinline__ void load_t64_gather(float (*S)[BM + 4], const float* __restrict__ x,
                                                const int* s_tok, int k0, int tid) {
#pragma unroll
    for (int j = 0; j < 2; j++) {
        int it = tid + j * NTH;
        int r = it >> 2, c4 = it & 3;
        const float* p = x + (size_t)s_tok[r] * HDIM + k0 + c4 * 4;
        float4 v = *(const float4*)p;
        S[c4 * 4 + 0][r] = v.x;
        S[c4 * 4 + 1][r] = v.y;
        S[c4 * 4 + 2][r] = v.z;
        S[c4 * 4 + 3][r] = v.w;
    }
}

// Load a 16(k) x 64(n) tile from [K,N] row-major src (row stride ldb), src points at (k=0, n0).
__device__ __forceinline__ void load_kn(float (*S)[BN + 4], const float* __restrict__ src,
                                        int ldb, int k0, int tid) {
#pragma unroll
    for (int j = 0; j < 2; j++) {
        int it = tid + j * NTH;
        int r = it >> 4, c4 = it & 15;
        float4 v = *(const float4*)(src + (size_t)(k0 + r) * ldb + c4 * 4);
        *(float4*)&S[r][c4 * 4] = v;
    }
}

// ---------------- kernels ----------------

__global__ void k_init() {
    if (threadIdx.x < NEXP) g_counts[threadIdx.x] = 0;
}

// C[M,N] = A[M,K] @ B[N,K]^T, plain store, ldC = N. PRECISE=1 -> 3xTF32.
template<int PRECISE>
__global__ __launch_bounds__(NTH) void k_gemm_nk(const float* __restrict__ A,
                                                 const float* __restrict__ B,
                                                 float* __restrict__ C,
                                                 int M, int N, int Kd) {
    __shared__ float As[BK][BM + 4];
    __shared__ float Bs[BK][BN + 4];
    int tid = threadIdx.x;
    int warp = tid >> 5, lane = tid & 31;
    int wm = warp >> 1, wn = warp & 1, gq = lane >> 2, tq = lane & 3;
    int m0 = blockIdx.y * BM, n0 = blockIdx.x * BN;
    const float* Ab = A + (size_t)m0 * Kd;
    const float* Bb = B + (size_t)n0 * Kd;

    float acc[2][4][4];
#pragma unroll
    for (int mt = 0; mt < 2; mt++)
#pragma unroll
        for (int nt = 0; nt < 4; nt++)
#pragma unroll
            for (int r = 0; r < 4; r++) acc[mt][nt][r] = 0.0f;

    for (int k0 = 0; k0 < Kd; k0 += BK) {
        __syncthreads();
        load_t64(As, Ab, Kd, k0, tid);
        load_t64(Bs, Bb, Kd, k0, tid);
        __syncthreads();
        mma_tile<PRECISE>(As, Bs, acc, wm, wn, gq, tq);
    }

#pragma unroll
    for (int mt = 0; mt < 2; mt++)
#pragma unroll
        for (int nt = 0; nt < 4; nt++)
#pragma unroll
            for (int r = 0; r < 4; r++) {
                int row = wm * 32 + mt * 16 + gq + ((r & 2) ? 8 : 0);
                int col = wn * 32 + nt * 8 + tq * 2 + (r & 1);
                C[(size_t)(m0 + row) * N + n0 + col] = acc[mt][nt][r];
            }
}

// shared experts up: shid = silu(x @ Wg^T) * (x @ Wu^T); Wg,Wu are [SI,H] ([N,K])
__global__ __launch_bounds__(NTH) void k_shared_up(const float* __restrict__ x,
                                                   const float* __restrict__ wg,
                                                   const float* __restrict__ wu) {
    __shared__ float As[BK][BM + 4];
    __shared__ float Bg[BK][BN + 4];
    __shared__ float Bu[BK][BN + 4];
    int tid = threadIdx.x;
    int warp = tid >> 5, lane = tid & 31;
    int wm = warp >> 1, wn = warp & 1, gq = lane >> 2, tq = lane & 3;
    int m0 = blockIdx.y * BM, n0 = blockIdx.x * BN;
    const float* Ab = x + (size_t)m0 * HDIM;
    const float* Gb = wg + (size_t)n0 * HDIM;
    const float* Ub = wu + (size_t)n0 * HDIM;

    float accg[2][4][4], accu[2][4][4];
#pragma unroll
    for (int mt = 0; mt < 2; mt++)
#pragma unroll
        for (int nt = 0; nt < 4; nt++)
#pragma unroll
            for (int r = 0; r < 4; r++) { accg[mt][nt][r] = 0.0f; accu[mt][nt][r] = 0.0f; }

    for (int k0 = 0; k0 < HDIM; k0 += BK) {
        __syncthreads();
        load_t64(As, Ab, HDIM, k0, tid);
        load_t64(Bg, Gb, HDIM, k0, tid);
        load_t64(Bu, Ub, HDIM, k0, tid);
        __syncthreads();
        mma_tile<0>(As, Bg, accg, wm, wn, gq, tq);
        mma_tile<0>(As, Bu, accu, wm, wn, gq, tq);
    }

#pragma unroll
    for (int mt = 0; mt < 2; mt++)
#pragma unroll
        for (int nt = 0; nt < 4; nt++)
#pragma unroll
            for (int r = 0; r < 4; r++) {
                int row = wm * 32 + mt * 16 + gq + ((r & 2) ? 8 : 0);
                int col = wn * 32 + nt * 8 + tq * 2 + (r & 1);
                float g = accg[mt][nt][r], u = accu[mt][nt][r];
                g_shid[(size_t)(m0 + row) * SIDIM + n0 + col] = silu_f(g) * u;
            }
}

// routed gate_up (fused SwiGLU): per expert, gathered A rows; W[e] is [H, 2I] ([K,N])
__global__ __launch_bounds__(NTH) void k_gate_up(const float* __restrict__ x,
                                                 const float* __restrict__ w) {
    int e = blockIdx.z;
    int cnt = g_counts[e];
    int m0 = blockIdx.y * BM;
    if (m0 >= cnt) return;
    int n0 = blockIdx.x * BN;

    __shared__ int s_tok[BM];
    __shared__ float As[BK][BM + 4];
    __shared__ float Bg[BK][BN + 4];
    __shared__ float Bu[BK][BN + 4];
    int tid = threadIdx.x;
    int warp = tid >> 5, lane = tid & 31;
    int wm = warp >> 1, wn = warp & 1, gq = lane >> 2, tq = lane & 3;
    if (tid < BM) s_tok[tid] = g_buf_tok[e * CAP + m0 + tid];
    const float* wb = w + (size_t)e * HDIM * TWOI;

    float accg[2][4][4], accu[2][4][4];
#pragma unroll
    for (int mt = 0; mt < 2; mt++)
#pragma unroll
        for (int nt = 0; nt < 4; nt++)
#pragma unroll
            for (int r = 0; r < 4; r++) { accg[mt][nt][r] = 0.0f; accu[mt][nt][r] = 0.0f; }

    for (int k0 = 0; k0 < HDIM; k0 += BK) {
        __syncthreads();
        load_t64_gather(As, x, s_tok, k0, tid);
        load_kn(Bg, wb + n0, TWOI, k0, tid);
        load_kn(Bu, wb + n0 + IDIM, TWOI, k0, tid);
        __syncthreads();
        mma_tile<0>(As, Bg, accg, wm, wn, gq, tq);
        mma_tile<0>(As, Bu, accu, wm, wn, gq, tq);
    }

#pragma unroll
    for (int mt = 0; mt < 2; mt++)
#pragma unroll
        for (int nt = 0; nt < 4; nt++)
#pragma unroll
            for (int r = 0; r < 4; r++) {
                int row = wm * 32 + mt * 16 + gq + ((r & 2) ? 8 : 0);
                int col = wn * 32 + nt * 8 + tq * 2 + (r & 1);
                int gm = m0 + row;
                if (gm < cnt) {
                    float g = accg[mt][nt][r], u = accu[mt][nt][r];
                    g_hid[((size_t)e * CAP + gm) * IDIM + n0 + col] = silu_f(g) * u;
                }
            }
}

// routed down: C = hid[e] @ W[e] ([I,H], [K,N]); scale by gate weight; atomicAdd into out
__global__ __launch_bounds__(NTH) void k_down(const float* __restrict__ w,
                                              float* __restrict__ out) {
    int e = blockIdx.z;
    int cnt = g_counts[e];
    int m0 = blockIdx.y * BM;
    if (m0 >= cnt) return;
    int n0 = blockIdx.x * BN;

    __shared__ int s_tok[BM];
    __shared__ float s_w[BM];
    __shared__ float As[BK][BM + 4];
    __shared__ float Bs[BK][BN + 4];
    int tid = threadIdx.x;
    int warp = tid >> 5, lane = tid & 31;
    int wm = warp >> 1, wn = warp & 1, gq = lane >> 2, tq = lane & 3;
    if (tid < BM) {
        s_tok[tid] = g_buf_tok[e * CAP + m0 + tid];
        s_w[tid]   = g_buf_w[e * CAP + m0 + tid];
    }
    const float* Ab = g_hid + ((size_t)e * CAP + m0) * IDIM;
    const float* wb = w + (size_t)e * IDIM * HDIM + n0;

    float acc[2][4][4];
#pragma unroll
    for (int mt = 0; mt < 2; mt++)
#pragma unroll
        for (int nt = 0; nt < 4; nt++)
#pragma unroll
            for (int r = 0; r < 4; r++) acc[mt][nt][r] = 0.0f;

    for (int k0 = 0; k0 < IDIM; k0 += BK) {
        __syncthreads();
        load_t64(As, Ab, IDIM, k0, tid);
        load_kn(Bs, wb, HDIM, k0, tid);
        __syncthreads();
        mma_tile<0>(As, Bs, acc, wm, wn, gq, tq);
    }

#pragma unroll
    for (int mt = 0; mt < 2; mt++)
#pragma unroll
        for (int nt = 0; nt < 4; nt++)
#pragma unroll
            for (int r = 0; r < 4; r++) {
                int row = wm * 32 + mt * 16 + gq + ((r & 2) ? 8 : 0);
                int col = wn * 32 + nt * 8 + tq * 2 + (r & 1);
                int gm = m0 + row;
                if (gm < cnt) {
                    atomicAdd(&out[(size_t)s_tok[row] * HDIM + n0 + col],
                              acc[mt][nt][r] * s_w[row]);
                }
            }
}

// router: softmax over 64 experts, greedy top-6, atomic slot dispatch. 1 warp per token.
__global__ void k_router() {
    int warp = threadIdx.x >> 5, lane = threadIdx.x & 31;
    int t = blockIdx.x * 8 + warp;
    float v0 = g_logits[t * NEXP + lane];
    float v1 = g_logits[t * NEXP + 32 + lane];
    float m = fmaxf(v0, v1);
#pragma unroll
    for (int s = 16; s > 0; s >>= 1) m = fmaxf(m, __shfl_xor_sync(0xffffffffu, m, s));
    float e0 = expf(v0 - m), e1 = expf(v1 - m);
    float sum = e0 + e1;
#pragma unroll
    for (int s = 16; s > 0; s >>= 1) sum += __shfl_xor_sync(0xffffffffu, sum, s);
    float inv = 1.0f / sum;
    float p0 = e0 * inv, p1 = e1 * inv;

#pragma unroll
    for (int k = 0; k < TOPK; k++) {
        float bv; int bi;
        if (p0 >= p1) { bv = p0; bi = lane; } else { bv = p1; bi = lane + 32; }
#pragma unroll
        for (int s = 16; s > 0; s >>= 1) {
            float ov = __shfl_xor_sync(0xffffffffu, bv, s);
            int   oi = __shfl_xor_sync(0xffffffffu, bi, s);
            if (ov > bv || (ov == bv && oi < bi)) { bv = ov; bi = oi; }
        }
        if (lane == 0) {
            int pos = atomicAdd(&g_counts[bi], 1);
            if (pos < CAP) {
                g_buf_tok[bi * CAP + pos] = t;
                g_buf_w[bi * CAP + pos] = bv;   // SCALE = 1.0
            }
        }
        if (bi < 32) { if (lane == bi) p0 = -1.0f; }
        else         { if (lane == bi - 32) p1 = -1.0f; }
    }
}

// ---------------- launch ----------------
extern "C" void kernel_launch(void* const* d_in, const int* in_sizes, int n_in,
                              void* d_out, int out_size) {
    const float* x   = (const float*)d_in[0];
    const float* gw  = (const float*)d_in[1];
    const float* gup = (const float*)d_in[2];
    const float* dwn = (const float*)d_in[3];
    const float* sgw = (const float*)d_in[4];
    const float* suw = (const float*)d_in[5];
    const float* sdw = (const float*)d_in[6];
    float* out = (float*)d_out;

    float* p_logits = nullptr;
    float* p_shid = nullptr;
    cudaGetSymbolAddress((void**)&p_logits, g_logits);
    cudaGetSymbolAddress((void**)&p_shid, g_shid);

    // 1. reset per-expert counters
    k_init<<<1, 64>>>();
    // 2. router logits in 3xTF32 (near-fp32 so top-k matches the reference)
    k_gemm_nk<1><<<dim3(NEXP / BN, NTOK / BM), NTH>>>(x, gw, p_logits, NTOK, NEXP, HDIM);
    // 3. softmax + top-6 + dispatch
    k_router<<<NTOK / 8, 256>>>();
    // 4. shared experts up (fused SwiGLU)
    k_shared_up<<<dim3(SIDIM / BN, NTOK / BM), NTH>>>(x, sgw, suw);
    // 5. shared experts down — plain stores, initializes every element of out
    k_gemm_nk<0><<<dim3(HDIM / BN, NTOK / BM), NTH>>>(p_shid, sdw, out, NTOK, HDIM, SIDIM);
    // 6. routed gate_up (gather + fused SwiGLU), early-exit on per-expert count
    k_gate_up<<<dim3(IDIM / BN, CAP / BM, NEXP), NTH>>>(x, gup);
    // 7. routed down + weighted scatter-add into out
    k_down<<<dim3(HDIM / BN, CAP / BM, NEXP), NTH>>>(dwn, out);
}

// round 2
// speedup vs baseline: 1.0048x; 1.0048x over previous
#include <cuda_runtime.h>
#include <math.h>
#include <stdint.h>

// ---------------- problem constants ----------------
#define NTOK   2048
#define NEXP   64
#define TOPK   6
#define CAP    512
#define HDIM   2048
#define IDIM   768
#define TWOI   1536
#define SIDIM  1536

// ---------------- main GEMM tile config ----------------
#define BM 64
#define BN 128
#define BK 16
#define NTH 256          // 8 warps: 2 (M) x 4 (N), warp tile 32x32
#define APAD 8           // As row = BM+8 = 72  (72 % 32 == 8 -> conflict-free frag reads)
#define BPAD 8           // Bs row = BN+8 = 136 (136 % 32 == 8)

// ---------------- scratch ----------------
__device__ int   g_counts[NEXP];
__device__ int   g_buf_tok[NEXP * CAP];
__device__ float g_buf_w[NEXP * CAP];
__device__ float g_logits[NTOK * NEXP];
__device__ float g_gu[(size_t)NEXP * CAP * TWOI];    // ~201 MB
__device__ float g_hid[(size_t)NEXP * CAP * IDIM];   // ~100 MB
__device__ float g_shg[(size_t)NTOK * SIDIM];
__device__ float g_shu[(size_t)NTOK * SIDIM];
__device__ float g_shid[(size_t)NTOK * SIDIM];

// ---------------- helpers ----------------
__device__ __forceinline__ unsigned f2tf(float x) {
    unsigned y;
    asm("cvt.rna.tf32.f32 %0, %1;" : "=r"(y) : "f"(x));
    return y;
}
__device__ __forceinline__ float tfs(float x) {   // tf32-rounded value as float bits
    return __uint_as_float(f2tf(x));
}
__device__ __forceinline__ void mma8(float c[4], const unsigned a[4], const unsigned b[2]) {
    asm volatile(
        "mma.sync.aligned.m16n8k8.row.col.f32.tf32.tf32.f32 "
        "{%0,%1,%2,%3}, {%4,%5,%6,%7}, {%8,%9}, {%0,%1,%2,%3};"
        : "+f"(c[0]), "+f"(c[1]), "+f"(c[2]), "+f"(c[3])
        : "r"(a[0]), "r"(a[1]), "r"(a[2]), "r"(a[3]), "r"(b[0]), "r"(b[1]));
}
__device__ __forceinline__ float silu_f(float v) { return v / (1.0f + expf(-v)); }

// ================= unified pipelined GEMM =================
// C[M,N] = A @ B.  A row-major [M,K] (lda=K).  BNK: B is [N,K]; else [K,N] (ldb=N).
// EXPERT: blockIdx.z = expert, rows limited by g_counts[e], A/B/C offset by per-expert strides.
// GATHER: A rows gathered from x via g_buf_tok.  ATOMIC: weighted atomic scatter-add epilogue.
template<int BNK, int EXPERT, int GATHER, int ATOMIC>
__global__ __launch_bounds__(NTH) void k_gemm(
    const float* __restrict__ Abase, const float* __restrict__ Bbase,
    float* __restrict__ C, int N, int Kd, int ldc,
    long sA, long sB, long sC)
{
    __shared__ float As[2][BK][BM + APAD];
    __shared__ float Bs[2][BK][BN + BPAD];
    __shared__ int   s_tok[BM];
    __shared__ float s_w[BM];

    const int tid  = threadIdx.x;
    const int warp = tid >> 5, lane = tid & 31;
    const int wm = warp >> 2, wn = warp & 3;      // 2 x 4 warp grid
    const int gq = lane >> 2, tq = lane & 3;
    const int m0 = blockIdx.y * BM, n0 = blockIdx.x * BN;

    int e = 0, cnt = 0x7fffffff;
    if (EXPERT) {
        e = blockIdx.z;
        cnt = g_counts[e];
        if (m0 >= cnt) return;
    }

    if (GATHER || ATOMIC) {
        if (tid < BM) {
            int p = m0 + tid;
            int ok = (p < cnt);
            s_tok[tid] = ok ? g_buf_tok[e * CAP + p] : 0;
            if (ATOMIC) s_w[tid] = ok ? g_buf_w[e * CAP + p] : 0.0f;
        }
        __syncthreads();
    }

    // ---- per-thread load indices ----
    const int ar  = tid >> 2;          // A row within tile (0..63)
    const int asel = tid & 3;          // k-quad selector (x4 floats)
    const int ak4 = asel * 4;
    const float* Arow;
    if (GATHER) Arow = Abase + (size_t)s_tok[ar] * Kd + ak4;
    else        Arow = Abase + (EXPERT ? (size_t)e * sA : 0) + (size_t)(m0 + ar) * Kd + ak4;

    const float* Bb = Bbase + (EXPERT ? (size_t)e * sB : 0)
                      + (BNK ? (size_t)n0 * Kd : (size_t)n0);

    float4 ra, rb0, rb1;

    // ---- stage loaders ----
    auto ldg = [&](int k0) {
        ra = *(const float4*)(Arow + k0);
        if (BNK) {
            int r = tid >> 2;                 // 0..63, then +64
            rb0 = *(const float4*)(Bb + (size_t)r        * Kd + k0 + ak4);
            rb1 = *(const float4*)(Bb + (size_t)(r + 64) * Kd + k0 + ak4);
        } else {
            int kr = tid >> 5;                // 0..7, then +8
            int nc = (tid & 31) * 4;
            rb0 = *(const float4*)(Bb + (size_t)(k0 + kr)     * N + nc);
            rb1 = *(const float4*)(Bb + (size_t)(k0 + kr + 8) * N + nc);
        }
    };
    auto sts = [&](int buf) {
        float ea[4] = {tfs(ra.x), tfs(ra.y), tfs(ra.z), tfs(ra.w)};
#pragma unroll
        for (int i = 0; i < 4; i++) {            // bank-rotated scatter
            int sel = (i + asel) & 3;
            As[buf][ak4 + sel][ar] = ea[sel];
        }
        if (BNK) {
            float eb0[4] = {tfs(rb0.x), tfs(rb0.y), tfs(rb0.z), tfs(rb0.w)};
            float eb1[4] = {tfs(rb1.x), tfs(rb1.y), tfs(rb1.z), tfs(rb1.w)};
            int r = tid >> 2;
#pragma unroll
            for (int i = 0; i < 4; i++) {
                int sel = (i + asel) & 3;
                Bs[buf][ak4 + sel][r]      = eb0[sel];
                Bs[buf][ak4 + sel][r + 64] = eb1[sel];
            }
        } else {
            int kr = tid >> 5;
            int nc = (tid & 31) * 4;
            float4 v0 = make_float4(tfs(rb0.x), tfs(rb0.y), tfs(rb0.z), tfs(rb0.w));
            float4 v1 = make_float4(tfs(rb1.x), tfs(rb1.y), tfs(rb1.z), tfs(rb1.w));
            *(float4*)&Bs[buf][kr][nc]     = v0;
            *(float4*)&Bs[buf][kr + 8][nc] = v1;
        }
    };

    float acc[2][4][4];
#pragma unroll
    for (int mt = 0; mt < 2; mt++)
#pragma unroll
        for (int nt = 0; nt < 4; nt++)
#pragma unroll
            for (int r = 0; r < 4; r++) acc[mt][nt][r] = 0.0f;

    const int nIter = Kd / BK;
    ldg(0);
    sts(0);

    for (int it = 0; it < nIter; it++) {
        __syncthreads();
        if (it + 1 < nIter) ldg((it + 1) * BK);

        const float (*pA)[BM + APAD] = As[it & 1];
        const float (*pB)[BN + BPAD] = Bs[it & 1];
#pragma unroll
        for (int kk = 0; kk < BK; kk += 8) {
            unsigned af[2][4], bf[4][2];
#pragma unroll
            for (int mt = 0; mt < 2; mt++) {
                int rb = wm * 32 + mt * 16;
                af[mt][0] = __float_as_uint(pA[kk + tq    ][rb + gq    ]);
                af[mt][1] = __float_as_uint(pA[kk + tq    ][rb + gq + 8]);
                af[mt][2] = __float_as_uint(pA[kk + tq + 4][rb + gq    ]);
                af[mt][3] = __float_as_uint(pA[kk + tq + 4][rb + gq + 8]);
            }
#pragma unroll
            for (int nt = 0; nt < 4; nt++) {
                int cb = wn * 32 + nt * 8 + gq;
                bf[nt][0] = __float_as_uint(pB[kk + tq    ][cb]);
                bf[nt][1] = __float_as_uint(pB[kk + tq + 4][cb]);
            }
#pragma unroll
            for (int mt = 0; mt < 2; mt++)
#pragma unroll
                for (int nt = 0; nt < 4; nt++)
                    mma8(acc[mt][nt], af[mt], bf[nt]);
        }
        if (it + 1 < nIter) {
            __syncthreads();
            sts((it + 1) & 1);
        }
    }

    // ---- epilogue ----
#pragma unroll
    for (int mt = 0; mt < 2; mt++)
#pragma unroll
        for (int nt = 0; nt < 4; nt++)
#pragma unroll
            for (int r = 0; r < 4; r++) {
                int row = wm * 32 + mt * 16 + gq + ((r & 2) ? 8 : 0);
                int col = wn * 32 + nt * 8 + tq * 2 + (r & 1);
                int gm = m0 + row;
                if (EXPERT && gm >= cnt) continue;
                if (ATOMIC) {
                    atomicAdd(&C[(size_t)s_tok[row] * ldc + n0 + col],
                              acc[mt][nt][r] * s_w[row]);
                } else {
                    float* dst = C + (EXPERT ? (size_t)e * sC : 0);
                    dst[(size_t)gm * ldc + n0 + col] = acc[mt][nt][r];
                }
            }
}

// ================= router logits: 3xTF32 (near-fp32) =================
#define RTH 128
__global__ __launch_bounds__(RTH) void k_router_gemm(const float* __restrict__ A,
                                                     const float* __restrict__ B,
                                                     float* __restrict__ C) {
    __shared__ float As[BK][64 + 4];
    __shared__ float Bsm[BK][64 + 4];
    int tid = threadIdx.x;
    int warp = tid >> 5, lane = tid & 31;
    int wm = warp >> 1, wn = warp & 1, gq = lane >> 2, tq = lane & 3;
    int m0 = blockIdx.y * 64, n0 = 0;

    const float* Ab = A + (size_t)m0 * HDIM;
    const float* Bb = B;

    float acc[2][4][4];
#pragma unroll
    for (int mt = 0; mt < 2; mt++)
#pragma unroll
        for (int nt = 0; nt < 4; nt++)
#pragma unroll
            for (int r = 0; r < 4; r++) acc[mt][nt][r] = 0.0f;

    for (int k0 = 0; k0 < HDIM; k0 += BK) {
        __syncthreads();
#pragma unroll
        for (int j = 0; j < 2; j++) {
            int it = tid + j * RTH;
            int r = it >> 2, c4 = it & 3;
            float4 va = *(const float4*)(Ab + (size_t)r * HDIM + k0 + c4 * 4);
            As[c4 * 4 + 0][r] = va.x; As[c4 * 4 + 1][r] = va.y;
            As[c4 * 4 + 2][r] = va.z; As[c4 * 4 + 3][r] = va.w;
            float4 vb = *(const float4*)(Bb + (size_t)r * HDIM + k0 + c4 * 4);
            Bsm[c4 * 4 + 0][r] = vb.x; Bsm[c4 * 4 + 1][r] = vb.y;
            Bsm[c4 * 4 + 2][r] = vb.z; Bsm[c4 * 4 + 3][r] = vb.w;
        }
        __syncthreads();
#pragma unroll
        for (int kk = 0; kk < BK; kk += 8) {
            float af[2][4], bfv[4][2];
#pragma unroll
            for (int mt = 0; mt < 2; mt++) {
                int rb = wm * 32 + mt * 16;
                af[mt][0] = As[kk + tq    ][rb + gq    ];
                af[mt][1] = As[kk + tq    ][rb + gq + 8];
                af[mt][2] = As[kk + tq + 4][rb + gq    ];
                af[mt][3] = As[kk + tq + 4][rb + gq + 8];
            }
#pragma unroll
            for (int nt = 0; nt < 4; nt++) {
                int cb = wn * 32 + nt * 8 + gq;
                bfv[nt][0] = Bsm[kk + tq    ][cb];
                bfv[nt][1] = Bsm[kk + tq + 4][cb];
            }
            unsigned ah[2][4], al[2][4], bh[4][2], bl[4][2];
#pragma unroll
            for (int mt = 0; mt < 2; mt++)
#pragma unroll
                for (int i = 0; i < 4; i++) {
                    ah[mt][i] = f2tf(af[mt][i]);
                    al[mt][i] = f2tf(af[mt][i] - __uint_as_float(ah[mt][i]));
                }
#pragma unroll
            for (int nt = 0; nt < 4; nt++)
#pragma unroll
                for (int i = 0; i < 2; i++) {
                    bh[nt][i] = f2tf(bfv[nt][i]);
                    bl[nt][i] = f2tf(bfv[nt][i] - __uint_as_float(bh[nt][i]));
                }
#pragma unroll
            for (int mt = 0; mt < 2; mt++)
#pragma unroll
                for (int nt = 0; nt < 4; nt++) {
                    mma8(acc[mt][nt], al[mt], bh[nt]);
                    mma8(acc[mt][nt], ah[mt], bl[nt]);
                    mma8(acc[mt][nt], ah[mt], bh[nt]);
                }
        }
    }
#pragma unroll
    for (int mt = 0; mt < 2; mt++)
#pragma unroll
        for (int nt = 0; nt < 4; nt++)
#pragma unroll
            for (int r = 0; r < 4; r++) {
                int row = wm * 32 + mt * 16 + gq + ((r & 2) ? 8 : 0);
                int col = wn * 32 + nt * 8 + tq * 2 + (r & 1);
                C[(size_t)(m0 + row) * NEXP + n0 + col] = acc[mt][nt][r];
            }
}

// ================= router softmax + top-6 + dispatch =================
__global__ void k_init() {
    if (threadIdx.x < NEXP) g_counts[threadIdx.x] = 0;
}

__global__ void k_router() {
    int warp = threadIdx.x >> 5, lane = threadIdx.x & 31;
    int t = blockIdx.x * 8 + warp;
    float v0 = g_logits[t * NEXP + lane];
    float v1 = g_logits[t * NEXP + 32 + lane];
    float m = fmaxf(v0, v1);
#pragma unroll
    for (int s = 16; s > 0; s >>= 1) m = fmaxf(m, __shfl_xor_sync(0xffffffffu, m, s));
    float e0 = expf(v0 - m), e1 = expf(v1 - m);
    float sum = e0 + e1;
#pragma unroll
    for (int s = 16; s > 0; s >>= 1) sum += __shfl_xor_sync(0xffffffffu, sum, s);
    float inv = 1.0f / sum;
    float p0 = e0 * inv, p1 = e1 * inv;

#pragma unroll
    for (int k = 0; k < TOPK; k++) {
        float bv; int bi;
        if (p0 >= p1) { bv = p0; bi = lane; } else { bv = p1; bi = lane + 32; }
#pragma unroll
        for (int s = 16; s > 0; s >>= 1) {
            float ov = __shfl_xor_sync(0xffffffffu, bv, s);
            int   oi = __shfl_xor_sync(0xffffffffu, bi, s);
            if (ov > bv || (ov == bv && oi < bi)) { bv = ov; bi = oi; }
        }
        if (lane == 0) {
            int pos = atomicAdd(&g_counts[bi], 1);
            if (pos < CAP) {
                g_buf_tok[bi * CAP + pos] = t;
                g_buf_w[bi * CAP + pos] = bv;
            }
        }
        if (bi < 32) { if (lane == bi) p0 = -1.0f; }
        else         { if (lane == bi - 32) p1 = -1.0f; }
    }
}

// ================= SiLU epilogues =================
__global__ void k_silu_shared() {
    size_t i = (size_t)blockIdx.x * blockDim.x + threadIdx.x;   // float4 index
    float4 g = ((const float4*)g_shg)[i];
    float4 u = ((const float4*)g_shu)[i];
    float4 o;
    o.x = silu_f(g.x) * u.x; o.y = silu_f(g.y) * u.y;
    o.z = silu_f(g.z) * u.z; o.w = silu_f(g.w) * u.w;
    ((float4*)g_shid)[i] = o;
}

__global__ void k_silu_routed() {   // <<<NEXP*CAP, IDIM/4>>>
    int row = blockIdx.x;           // e*CAP + c
    int c4 = threadIdx.x;           // 0..191
    int e = row >> 9, c = row & (CAP - 1);
    float4 o = make_float4(0.f, 0.f, 0.f, 0.f);
    if (c < g_counts[e]) {
        const float* gu = g_gu + (size_t)row * TWOI;
        float4 g = *(const float4*)(gu + c4 * 4);
        float4 u = *(const float4*)(gu + IDIM + c4 * 4);
        o.x = silu_f(g.x) * u.x; o.y = silu_f(g.y) * u.y;
        o.z = silu_f(g.z) * u.z; o.w = silu_f(g.w) * u.w;
    }
    ((float4*)g_hid)[(size_t)row * (IDIM / 4) + c4] = o;
}

// ================= launch =================
extern "C" void kernel_launch(void* const* d_in, const int* in_sizes, int n_in,
                              void* d_out, int out_size) {
    const float* x   = (const float*)d_in[0];
    const float* gw  = (const float*)d_in[1];
    const float* gup = (const float*)d_in[2];
    const float* dwn = (const float*)d_in[3];
    const float* sgw = (const float*)d_in[4];
    const float* suw = (const float*)d_in[5];
    const float* sdw = (const float*)d_in[6];
    float* out = (float*)d_out;

    float *p_logits, *p_gu, *p_hid, *p_shg, *p_shu, *p_shid;
    cudaGetSymbolAddress((void**)&p_logits, g_logits);
    cudaGetSymbolAddress((void**)&p_gu,   g_gu);
    cudaGetSymbolAddress((void**)&p_hid,  g_hid);
    cudaGetSymbolAddress((void**)&p_shg,  g_shg);
    cudaGetSymbolAddress((void**)&p_shu,  g_shu);
    cudaGetSymbolAddress((void**)&p_shid, g_shid);

    k_init<<<1, 64>>>();
    // router: near-fp32 logits so top-k matches reference exactly
    k_router_gemm<<<dim3(1, NTOK / 64), RTH>>>(x, gw, p_logits);
    k_router<<<NTOK / 8, 256>>>();

    // shared experts: g = x@sgw^T, u = x@suw^T ([N,K] weights), silu, down -> out (plain store)
    k_gemm<1,0,0,0><<<dim3(SIDIM / BN, NTOK / BM), NTH>>>(x, sgw, p_shg, SIDIM, HDIM, SIDIM, 0, 0, 0);
    k_gemm<1,0,0,0><<<dim3(SIDIM / BN, NTOK / BM), NTH>>>(x, suw, p_shu, SIDIM, HDIM, SIDIM, 0, 0, 0);
    k_silu_shared<<<(NTOK * SIDIM / 4) / 256, 256>>>();
    k_gemm<1,0,0,0><<<dim3(HDIM / BN, NTOK / BM), NTH>>>(p_shid, sdw, out, HDIM, SIDIM, HDIM, 0, 0, 0);

    // routed experts: gate_up ([K,N] weights, gathered A), silu, down (atomic scatter-add)
    k_gemm<0,1,1,0><<<dim3(TWOI / BN, CAP / BM, NEXP), NTH>>>(
        x, gup, p_gu, TWOI, HDIM, TWOI, 0, (long)HDIM * TWOI, (long)CAP * TWOI);
    k_silu_routed<<<NEXP * CAP, IDIM / 4>>>();
    k_gemm<0,1,0,1><<<dim3(HDIM / BN, CAP / BM, NEXP), NTH>>>(
        p_hid, dwn, out, HDIM, IDIM, HDIM, (long)CAP * IDIM, (long)IDIM * HDIM, 0);
}

// round 4
// speedup vs baseline: 1.4608x; 1.4538x over previous
#include <cuda_runtime.h>
#include <math.h>
#include <stdint.h>

// ---------------- problem constants ----------------
#define NTOK   2048
#define NEXP   64
#define TOPK   6
#define CAP    512
#define HDIM   2048
#define IDIM   768
#define TWOI   1536
#define SIDIM  1536

// ---------------- GEMM tile config ----------------
#define BM 128
#define BN 128
#define BK 16
#define NTH 128              // 4 warps, 2x2, warp tile 64x64
#define LDSW 136             // smem row stride (words), 136 % 32 == 8

// swizzled word index for element (k, i) in a k-major tile
#define SWZ(k, i) ((k) * LDSW + ((i) ^ ((((k) >> 2) & 3) << 3)))

// ---------------- scratch ----------------
__device__ int   g_counts[NEXP];
__device__ int   g_buf_tok[NEXP * CAP];
__device__ float g_buf_w[NEXP * CAP];
__device__ float g_logits[NTOK * NEXP];
__device__ float g_gu[(size_t)NEXP * CAP * TWOI];
__device__ float g_hid[(size_t)NEXP * CAP * IDIM];
__device__ float g_shg[(size_t)NTOK * SIDIM];
__device__ float g_shu[(size_t)NTOK * SIDIM];
__device__ float g_shid[(size_t)NTOK * SIDIM];

// ---------------- helpers ----------------
__device__ __forceinline__ unsigned f2tf(float x) {
    unsigned y;
    asm("cvt.rna.tf32.f32 %0, %1;" : "=r"(y) : "f"(x));
    return y;
}
__device__ __forceinline__ float tfs(float x) { return __uint_as_float(f2tf(x)); }
__device__ __forceinline__ void mma8(float c[4], const unsigned a[4], const unsigned b[2]) {
    asm volatile(
        "mma.sync.aligned.m16n8k8.row.col.f32.tf32.tf32.f32 "
        "{%0,%1,%2,%3}, {%4,%5,%6,%7}, {%8,%9}, {%0,%1,%2,%3};"
        : "+f"(c[0]), "+f"(c[1]), "+f"(c[2]), "+f"(c[3])
        : "r"(a[0]), "r"(a[1]), "r"(a[2]), "r"(a[3]), "r"(b[0]), "r"(b[1]));
}
__device__ __forceinline__ float silu_f(float v) { return v / (1.0f + expf(-v)); }

// ================= mma.sync tf32 GEMM (128x128 block, 64x64 warp) =================
// C[M,N] = A[M,K] @ op(B).  BNK=1: B is [N,K] row-major.  BNK=0: B is [K,N] (ldb).
// EXPERT: blockIdx.z = expert (row count g_counts[e], strides sA/sB/sC).
// GATHER: A rows gathered from x via g_buf_tok.  ATOMIC: weighted atomic scatter-add.
template<int BNK, int EXPERT, int GATHER, int ATOMIC>
__global__ __launch_bounds__(NTH) void k_gemm(
    const float* __restrict__ Abase, const float* __restrict__ Bbase,
    float* __restrict__ C, int Kd, int ldb, int ldc,
    long sA, long sB, long sC)
{
    __shared__ float As[2][BK * LDSW];
    __shared__ float Bs[2][BK * LDSW];
    __shared__ int   s_tok[BM];
    __shared__ float s_w[BM];

    const int tid = threadIdx.x;
    const int warp = tid >> 5, lane = tid & 31;
    const int wm = warp >> 1, wn = warp & 1;     // 2x2 warp grid
    const int gq = lane >> 2, tq = lane & 3;
    const int m0 = blockIdx.y * BM, n0 = blockIdx.x * BN;

    int e = 0, cnt = 0x40000000;
    if (EXPERT) {
        e = blockIdx.z;
        cnt = g_counts[e];
        if (m0 >= cnt) return;
    }
    if (GATHER || ATOMIC) {
        if (tid < BM) {
            int p = m0 + tid;
            int ok = (p < cnt);
            s_tok[tid] = ok ? g_buf_tok[e * CAP + p] : 0;
            if (ATOMIC) s_w[tid] = ok ? g_buf_w[e * CAP + p] : 0.0f;
        }
        __syncthreads();
    }

    // ---- per-thread source pointers (bumped by BK each slab; no per-load IMAD.WIDE) ----
    // A loader (and BNK=1 B loader): idx = tid + j*NTH -> row = idx>>2, asel = idx&3
    const float* pa[4];
    const float* pb[4];
    const int asel = tid & 3;
    const int axor = asel << 3;
#pragma unroll
    for (int j = 0; j < 4; j++) {
        int idx = tid + j * NTH;
        int r = idx >> 2;
        if (GATHER) pa[j] = Abase + (size_t)s_tok[r] * Kd + asel * 4;
        else        pa[j] = Abase + (EXPERT ? (size_t)e * sA : 0)
                            + (size_t)(m0 + r) * Kd + asel * 4;
    }
    if (BNK) {
#pragma unroll
        for (int j = 0; j < 4; j++) {
            int idx = tid + j * NTH;
            int r = idx >> 2;
            pb[j] = Bbase + (EXPERT ? (size_t)e * sB : 0)
                    + (size_t)(n0 + r) * Kd + asel * 4;
        }
    } else {
#pragma unroll
        for (int j = 0; j < 4; j++) {
            int idx = tid + j * NTH;
            int kr = idx >> 5;               // 0..15
            int nc = (idx & 31) * 4;
            pb[j] = Bbase + (EXPERT ? (size_t)e * sB : 0)
                    + (size_t)kr * ldb + n0 + nc;
        }
    }
    const long bumpB = BNK ? (long)BK : (long)BK * ldb;

    // smem store targets (constant per thread)
    const int a_r0 = (tid >> 2);                         // rows r0, r0+32, r0+64, r0+96
    const int b_kr = tid >> 5;                           // BNK=0: k rows kr, kr+4, kr+8, kr+12
    const int b_nc = (tid & 31) * 4;

    float4 ra[4], rb[4];
    auto LDG = [&]() {
#pragma unroll
        for (int j = 0; j < 4; j++) ra[j] = *(const float4*)pa[j];
#pragma unroll
        for (int j = 0; j < 4; j++) rb[j] = *(const float4*)pb[j];
#pragma unroll
        for (int j = 0; j < 4; j++) { pa[j] += BK; pb[j] += bumpB; }
    };
    auto STS = [&](int buf) {
        float* A = As[buf];
        float* B = Bs[buf];
#pragma unroll
        for (int j = 0; j < 4; j++) {
            int r = a_r0 + j * 32;
            float* d = &A[asel * 4 * LDSW + (r ^ axor)];
            d[0]        = tfs(ra[j].x);
            d[LDSW]     = tfs(ra[j].y);
            d[2 * LDSW] = tfs(ra[j].z);
            d[3 * LDSW] = tfs(ra[j].w);
        }
        if (BNK) {
#pragma unroll
            for (int j = 0; j < 4; j++) {
                int r = a_r0 + j * 32;
                float* d = &B[asel * 4 * LDSW + (r ^ axor)];
                d[0]        = tfs(rb[j].x);
                d[LDSW]     = tfs(rb[j].y);
                d[2 * LDSW] = tfs(rb[j].z);
                d[3 * LDSW] = tfs(rb[j].w);
            }
        } else {
#pragma unroll
            for (int j = 0; j < 4; j++) {
                int kr = b_kr + j * 4;
                float4 v = make_float4(tfs(rb[j].x), tfs(rb[j].y), tfs(rb[j].z), tfs(rb[j].w));
                *(float4*)&B[kr * LDSW + (b_nc ^ (((kr >> 2) & 3) << 3))] = v;
            }
        }
    };

    float acc[4][8][4];
#pragma unroll
    for (int mt = 0; mt < 4; mt++)
#pragma unroll
        for (int nt = 0; nt < 8; nt++)
#pragma unroll
            for (int r = 0; r < 4; r++) acc[mt][nt][r] = 0.0f;

    const int nslab = Kd / BK;
    LDG();
    STS(0);
    __syncthreads();

    for (int s = 0; s < nslab; s++) {
        const int buf = s & 1;
        if (s + 1 < nslab) LDG();

        const float* A = As[buf];
        const float* B = Bs[buf];
#pragma unroll
        for (int kk = 0; kk < BK; kk += 8) {
            unsigned af[4][4], bf[8][2];
#pragma unroll
            for (int mt = 0; mt < 4; mt++) {
                int rb0 = wm * 64 + mt * 16 + gq;
                af[mt][0] = __float_as_uint(A[SWZ(kk + tq,     rb0)]);
                af[mt][1] = __float_as_uint(A[SWZ(kk + tq,     rb0 + 8)]);
                af[mt][2] = __float_as_uint(A[SWZ(kk + tq + 4, rb0)]);
                af[mt][3] = __float_as_uint(A[SWZ(kk + tq + 4, rb0 + 8)]);
            }
#pragma unroll
            for (int nt = 0; nt < 8; nt++) {
                int cb = wn * 64 + nt * 8 + gq;
                bf[nt][0] = __float_as_uint(B[SWZ(kk + tq,     cb)]);
                bf[nt][1] = __float_as_uint(B[SWZ(kk + tq + 4, cb)]);
            }
#pragma unroll
            for (int mt = 0; mt < 4; mt++)
#pragma unroll
                for (int nt = 0; nt < 8; nt++)
                    mma8(acc[mt][nt], af[mt], bf[nt]);
        }
        if (s + 1 < nslab) {
            __syncthreads();
            STS((s + 1) & 1);
            __syncthreads();
        }
    }

    // ---- epilogue ----
#pragma unroll
    for (int mt = 0; mt < 4; mt++) {
#pragma unroll
        for (int nt = 0; nt < 8; nt++) {
#pragma unroll
            for (int r = 0; r < 4; r++) {
                int row = wm * 64 + mt * 16 + gq + ((r & 2) ? 8 : 0);
                int col = wn * 64 + nt * 8 + tq * 2 + (r & 1);
                int gm = m0 + row;
                if (EXPERT && gm >= cnt) continue;
                if (ATOMIC) {
                    atomicAdd(&C[(size_t)s_tok[row] * ldc + n0 + col],
                              acc[mt][nt][r] * s_w[row]);
                } else {
                    float* dst = C + (EXPERT ? (size_t)e * sC : 0);
                    dst[(size_t)gm * ldc + n0 + col] = acc[mt][nt][r];
                }
            }
        }
    }
}

// ================= router logits: 3xTF32 (near-fp32) =================
#define RTH 128
__global__ __launch_bounds__(RTH) void k_router_gemm(const float* __restrict__ A,
                                                     const float* __restrict__ B,
                                                     float* __restrict__ C) {
    __shared__ float As[16][64 + 4];
    __shared__ float Bsm[16][64 + 4];
    int tid = threadIdx.x;
    int warp = tid >> 5, lane = tid & 31;
    int wm = warp >> 1, wn = warp & 1, gq = lane >> 2, tq = lane & 3;
    int m0 = blockIdx.y * 64;

    const float* Ab = A + (size_t)m0 * HDIM;
    const float* Bb = B;

    float acc[2][4][4];
#pragma unroll
    for (int mt = 0; mt < 2; mt++)
#pragma unroll
        for (int nt = 0; nt < 4; nt++)
#pragma unroll
            for (int r = 0; r < 4; r++) acc[mt][nt][r] = 0.0f;

    for (int k0 = 0; k0 < HDIM; k0 += 16) {
        __syncthreads();
#pragma unroll
        for (int j = 0; j < 2; j++) {
            int it = tid + j * RTH;
            int r = it >> 2, c4 = it & 3;
            float4 va = *(const float4*)(Ab + (size_t)r * HDIM + k0 + c4 * 4);
            As[c4 * 4 + 0][r] = va.x; As[c4 * 4 + 1][r] = va.y;
            As[c4 * 4 + 2][r] = va.z; As[c4 * 4 + 3][r] = va.w;
            float4 vb = *(const float4*)(Bb + (size_t)r * HDIM + k0 + c4 * 4);
            Bsm[c4 * 4 + 0][r] = vb.x; Bsm[c4 * 4 + 1][r] = vb.y;
            Bsm[c4 * 4 + 2][r] = vb.z; Bsm[c4 * 4 + 3][r] = vb.w;
        }
        __syncthreads();
#pragma unroll
        for (int kk = 0; kk < 16; kk += 8) {
            float af[2][4], bfv[4][2];
#pragma unroll
            for (int mt = 0; mt < 2; mt++) {
                int rb = wm * 32 + mt * 16;
                af[mt][0] = As[kk + tq    ][rb + gq    ];
                af[mt][1] = As[kk + tq    ][rb + gq + 8];
                af[mt][2] = As[kk + tq + 4][rb + gq    ];
                af[mt][3] = As[kk + tq + 4][rb + gq + 8];
            }
#pragma unroll
            for (int nt = 0; nt < 4; nt++) {
                int cb = wn * 32 + nt * 8 + gq;
                bfv[nt][0] = Bsm[kk + tq    ][cb];
                bfv[nt][1] = Bsm[kk + tq + 4][cb];
            }
            unsigned ah[2][4], al[2][4], bh[4][2], bl[4][2];
#pragma unroll
            for (int mt = 0; mt < 2; mt++)
#pragma unroll
                for (int i = 0; i < 4; i++) {
                    ah[mt][i] = f2tf(af[mt][i]);
                    al[mt][i] = f2tf(af[mt][i] - __uint_as_float(ah[mt][i]));
                }
#pragma unroll
            for (int nt = 0; nt < 4; nt++)
#pragma unroll
                for (int i = 0; i < 2; i++) {
                    bh[nt][i] = f2tf(bfv[nt][i]);
                    bl[nt][i] = f2tf(bfv[nt][i] - __uint_as_float(bh[nt][i]));
                }
#pragma unroll
            for (int mt = 0; mt < 2; mt++)
#pragma unroll
                for (int nt = 0; nt < 4; nt++) {
                    mma8(acc[mt][nt], al[mt], bh[nt]);
                    mma8(acc[mt][nt], ah[mt], bl[nt]);
                    mma8(acc[mt][nt], ah[mt], bh[nt]);
                }
        }
    }
#pragma unroll
    for (int mt = 0; mt < 2; mt++)
#pragma unroll
        for (int nt = 0; nt < 4; nt++)
#pragma unroll
            for (int r = 0; r < 4; r++) {
                int row = wm * 32 + mt * 16 + gq + ((r & 2) ? 8 : 0);
                int col = wn * 32 + nt * 8 + tq * 2 + (r & 1);
                C[(size_t)(m0 + row) * NEXP + col] = acc[mt][nt][r];
            }
}

// ================= router softmax + top-6 + dispatch =================
__global__ void k_init() {
    if (threadIdx.x < NEXP) g_counts[threadIdx.x] = 0;
}

__global__ void k_router() {
    int warp = threadIdx.x >> 5, lane = threadIdx.x & 31;
    int t = blockIdx.x * 8 + warp;
    float v0 = g_logits[t * NEXP + lane];
    float v1 = g_logits[t * NEXP + 32 + lane];
    float m = fmaxf(v0, v1);
#pragma unroll
    for (int s = 16; s > 0; s >>= 1) m = fmaxf(m, __shfl_xor_sync(0xffffffffu, m, s));
    float e0 = expf(v0 - m), e1 = expf(v1 - m);
    float sum = e0 + e1;
#pragma unroll
    for (int s = 16; s > 0; s >>= 1) sum += __shfl_xor_sync(0xffffffffu, sum, s);
    float inv = 1.0f / sum;
    float p0 = e0 * inv, p1 = e1 * inv;

#pragma unroll
    for (int k = 0; k < TOPK; k++) {
        float bv; int bi;
        if (p0 >= p1) { bv = p0; bi = lane; } else { bv = p1; bi = lane + 32; }
#pragma unroll
        for (int s = 16; s > 0; s >>= 1) {
            float ov = __shfl_xor_sync(0xffffffffu, bv, s);
            int   oi = __shfl_xor_sync(0xffffffffu, bi, s);
            if (ov > bv || (ov == bv && oi < bi)) { bv = ov; bi = oi; }
        }
        if (lane == 0) {
            int pos = atomicAdd(&g_counts[bi], 1);
            if (pos < CAP) {
                g_buf_tok[bi * CAP + pos] = t;
                g_buf_w[bi * CAP + pos] = bv;
            }
        }
        if (bi < 32) { if (lane == bi) p0 = -1.0f; }
        else         { if (lane == bi - 32) p1 = -1.0f; }
    }
}

// ================= SiLU epilogues =================
__global__ void k_silu_shared() {
    size_t i = (size_t)blockIdx.x * blockDim.x + threadIdx.x;
    float4 g = ((const float4*)g_shg)[i];
    float4 u = ((const float4*)g_shu)[i];
    float4 o;
    o.x = silu_f(g.x) * u.x; o.y = silu_f(g.y) * u.y;
    o.z = silu_f(g.z) * u.z; o.w = silu_f(g.w) * u.w;
    ((float4*)g_shid)[i] = o;
}

__global__ void k_silu_routed() {   // <<<NEXP*CAP, IDIM/4>>>
    int row = blockIdx.x;           // e*CAP + c
    int c4 = threadIdx.x;           // 0..191
    int e = row >> 9, c = row & (CAP - 1);
    float4 o = make_float4(0.f, 0.f, 0.f, 0.f);
    if (c < g_counts[e]) {
        const float* gu = g_gu + (size_t)row * TWOI;
        float4 g = *(const float4*)(gu + c4 * 4);
        float4 u = *(const float4*)(gu + IDIM + c4 * 4);
        o.x = silu_f(g.x) * u.x; o.y = silu_f(g.y) * u.y;
        o.z = silu_f(g.z) * u.z; o.w = silu_f(g.w) * u.w;
    }
    ((float4*)g_hid)[(size_t)row * (IDIM / 4) + c4] = o;
}

// ================= launch =================
extern "C" void kernel_launch(void* const* d_in, const int* in_sizes, int n_in,
                              void* d_out, int out_size) {
    const float* x   = (const float*)d_in[0];
    const float* gw  = (const float*)d_in[1];
    const float* gup = (const float*)d_in[2];
    const float* dwn = (const float*)d_in[3];
    const float* sgw = (const float*)d_in[4];
    const float* suw = (const float*)d_in[5];
    const float* sdw = (const float*)d_in[6];
    float* out = (float*)d_out;

    float *p_logits, *p_gu, *p_hid, *p_shg, *p_shu, *p_shid;
    cudaGetSymbolAddress((void**)&p_logits, g_logits);
    cudaGetSymbolAddress((void**)&p_gu,   g_gu);
    cudaGetSymbolAddress((void**)&p_hid,  g_hid);
    cudaGetSymbolAddress((void**)&p_shg,  g_shg);
    cudaGetSymbolAddress((void**)&p_shu,  g_shu);
    cudaGetSymbolAddress((void**)&p_shid, g_shid);

    k_init<<<1, 64>>>();
    // router: near-fp32 logits so top-k matches reference exactly
    k_router_gemm<<<dim3(1, NTOK / 64), RTH>>>(x, gw, p_logits);
    k_router<<<NTOK / 8, 256>>>();

    // shared experts (weights [N,K]): g, u, silu, then down -> out (plain store covers out)
    k_gemm<1,0,0,0><<<dim3(SIDIM / BN, NTOK / BM), NTH>>>(
        x, sgw, p_shg, HDIM, 0, SIDIM, 0, 0, 0);
    k_gemm<1,0,0,0><<<dim3(SIDIM / BN, NTOK / BM), NTH>>>(
        x, suw, p_shu, HDIM, 0, SIDIM, 0, 0, 0);
    k_silu_shared<<<(NTOK * SIDIM / 4) / 256, 256>>>();
    k_gemm<1,0,0,0><<<dim3(HDIM / BN, NTOK / BM), NTH>>>(
        p_shid, sdw, out, SIDIM, 0, HDIM, 0, 0, 0);

    // routed experts: gate_up (gathered A, weights [K,N]), silu, down (atomic scatter-add)
    k_gemm<0,1,1,0><<<dim3(TWOI / BN, CAP / BM, NEXP), NTH>>>(
        x, gup, p_gu, HDIM, TWOI, TWOI, 0, (long)HDIM * TWOI, (long)CAP * TWOI);
    k_silu_routed<<<NEXP * CAP, IDIM / 4>>>();
    k_gemm<0,1,0,1><<<dim3(HDIM / BN, CAP / BM, NEXP), NTH>>>(
        p_hid, dwn, out, IDIM, HDIM, HDIM, (long)CAP * IDIM, (long)IDIM * HDIM, 0);
}

// round 5
// speedup vs baseline: 1.4749x; 1.0097x over previous
#include <cuda_runtime.h>
#include <math.h>
#include <stdint.h>

// ---------------- problem constants ----------------
#define NTOK   2048
#define NEXP   64
#define TOPK   6
#define CAP    512
#define HDIM   2048
#define IDIM   768
#define TWOI   1536
#define SIDIM  1536

// ---------------- GEMM tile config ----------------
#define BM 128
#define BN 128
#define BK 16
#define NTH 256              // 8 warps: 2(M) x 4(N), warp tile 64x32
#define NSTG 4               // cp.async pipeline stages
#define LDA 20               // [row][k] stride in words (16 + 4 pad) -> conflict-free frags
#define LDBK 136             // [k][n] stride in words (128 + 8 pad) -> conflict-free frags
#define ASTG 2560            // words per stage per operand (128*20; >= 16*136)
#define SMEM_DYN (NSTG * ASTG * 2 * 4)   // 81920 bytes

// ---------------- scratch ----------------
__device__ int   g_counts[NEXP];
__device__ int   g_buf_tok[NEXP * CAP];
__device__ float g_buf_w[NEXP * CAP];
__device__ float g_logits[NTOK * NEXP];
__device__ float g_gu[(size_t)NEXP * CAP * TWOI];
__device__ float g_hid[(size_t)NEXP * CAP * IDIM];
__device__ float g_shg[(size_t)NTOK * SIDIM];
__device__ float g_shu[(size_t)NTOK * SIDIM];
__device__ float g_shid[(size_t)NTOK * SIDIM];

// ---------------- helpers ----------------
__device__ __forceinline__ unsigned f2tf(float x) {
    unsigned y;
    asm("cvt.rna.tf32.f32 %0, %1;" : "=r"(y) : "f"(x));
    return y;
}
__device__ __forceinline__ void mma8(float c[4], const unsigned a[4], const unsigned b[2]) {
    asm volatile(
        "mma.sync.aligned.m16n8k8.row.col.f32.tf32.tf32.f32 "
        "{%0,%1,%2,%3}, {%4,%5,%6,%7}, {%8,%9}, {%0,%1,%2,%3};"
        : "+f"(c[0]), "+f"(c[1]), "+f"(c[2]), "+f"(c[3])
        : "r"(a[0]), "r"(a[1]), "r"(a[2]), "r"(a[3]), "r"(b[0]), "r"(b[1]));
}
__device__ __forceinline__ float silu_f(float v) { return v / (1.0f + expf(-v)); }

__device__ __forceinline__ uint32_t smem_u32(const void* p) {
    uint32_t a;
    asm("{ .reg .u64 t; cvta.to.shared.u64 t, %1; cvt.u32.u64 %0, t; }" : "=r"(a) : "l"(p));
    return a;
}
__device__ __forceinline__ void cpasync16(uint32_t sdst, const void* gsrc) {
    asm volatile("cp.async.cg.shared.global [%0], [%1], 16;" :: "r"(sdst), "l"(gsrc) : "memory");
}
#define CP_COMMIT() asm volatile("cp.async.commit_group;" ::: "memory")
#define CP_WAIT2()  asm volatile("cp.async.wait_group 2;" ::: "memory")

// ================= cp.async-pipelined mma.sync tf32 GEMM =================
// C[M,N] = A[M,K] @ op(B).  BNK=1: B is [N,K] row-major.  BNK=0: B is [K,N] (ldb).
// EXPERT: blockIdx.z = expert (row count g_counts[e], strides sA/sB/sC).
// GATHER: A rows gathered from x via g_buf_tok.  ATOMIC: weighted atomic scatter-add.
template<int BNK, int EXPERT, int GATHER, int ATOMIC>
__global__ __launch_bounds__(NTH, 2) void k_gemm(
    const float* __restrict__ Abase, const float* __restrict__ Bbase,
    float* __restrict__ C, int Kd, int ldb, int ldc,
    long sA, long sB, long sC)
{
    extern __shared__ float sm[];
    __shared__ int   s_tok[BM];
    __shared__ float s_w[BM];

    const int tid = threadIdx.x;
    const int warp = tid >> 5, lane = tid & 31;
    const int wm = warp >> 2, wn = warp & 3;     // 2 x 4 warp grid (64x32 warp tile)
    const int gq = lane >> 2, tq = lane & 3;
    const int m0 = blockIdx.y * BM, n0 = blockIdx.x * BN;

    int e = 0, cnt = 0x40000000;
    if (EXPERT) {
        e = blockIdx.z;
        cnt = g_counts[e];
        if (m0 >= cnt) return;
    }
    if (GATHER || ATOMIC) {
        if (tid < BM) {
            int p = m0 + tid;
            int ok = (p < cnt);
            s_tok[tid] = ok ? g_buf_tok[e * CAP + p] : 0;
            if (ATOMIC) s_w[tid] = ok ? g_buf_w[e * CAP + p] : 0.0f;
        }
        __syncthreads();
    }

    const uint32_t smA = smem_u32(sm);
    const uint32_t smB = smA + NSTG * ASTG * 4;

    // ---- cp.async source pointers + smem byte offsets (2 chunks each for A and B) ----
    const float* pa[2];
    const float* pb[2];
    uint32_t da[2], db[2];
#pragma unroll
    for (int j = 0; j < 2; j++) {
        int idx = tid + j * NTH;            // 0..511
        int m = idx >> 2, k4 = (idx & 3) * 4;
        if (GATHER) pa[j] = Abase + (size_t)s_tok[m] * Kd + k4;
        else        pa[j] = Abase + (EXPERT ? (size_t)e * sA : 0) + (size_t)(m0 + m) * Kd + k4;
        da[j] = (uint32_t)(m * LDA + k4) * 4;
        if (BNK) {
            pb[j] = Bbase + (EXPERT ? (size_t)e * sB : 0) + (size_t)(n0 + m) * Kd + k4;
            db[j] = (uint32_t)(m * LDA + k4) * 4;
        } else {
            int kr = idx >> 5, nc = (idx & 31) * 4;
            pb[j] = Bbase + (EXPERT ? (size_t)e * sB : 0) + (size_t)kr * ldb + n0 + nc;
            db[j] = (uint32_t)(kr * LDBK + nc) * 4;
        }
    }
    const long bumpB = BNK ? (long)BK : (long)BK * ldb;

    auto issue = [&](int s) {
        uint32_t stoff = (uint32_t)(s & (NSTG - 1)) * (ASTG * 4);
#pragma unroll
        for (int j = 0; j < 2; j++) { cpasync16(smA + stoff + da[j], pa[j]); pa[j] += BK; }
#pragma unroll
        for (int j = 0; j < 2; j++) { cpasync16(smB + stoff + db[j], pb[j]); pb[j] += bumpB; }
        CP_COMMIT();
    };

    float acc[4][4][4];
#pragma unroll
    for (int mt = 0; mt < 4; mt++)
#pragma unroll
        for (int nt = 0; nt < 4; nt++)
#pragma unroll
            for (int r = 0; r < 4; r++) acc[mt][nt][r] = 0.0f;

    const int nslab = Kd / BK;
    issue(0); issue(1); issue(2);

    // precomputed fragment row offsets (words)
    int aoff[4];
#pragma unroll
    for (int mt = 0; mt < 4; mt++) aoff[mt] = (wm * 64 + mt * 16 + gq) * LDA;
    int boff[4];
#pragma unroll
    for (int nt = 0; nt < 4; nt++)
        boff[nt] = BNK ? (wn * 32 + nt * 8 + gq) * LDA : (wn * 32 + nt * 8 + gq);

    for (int s = 0; s < nslab; s++) {
        CP_WAIT2();
        __syncthreads();
        if (s + 3 < nslab) issue(s + 3);

        const float* A = sm + (s & (NSTG - 1)) * ASTG;
        const float* B = sm + NSTG * ASTG + (s & (NSTG - 1)) * ASTG;
#pragma unroll
        for (int kk = 0; kk < BK; kk += 8) {
            unsigned af[4][4], bf[4][2];
#pragma unroll
            for (int mt = 0; mt < 4; mt++) {
                af[mt][0] = f2tf(A[aoff[mt] + kk + tq]);
                af[mt][1] = f2tf(A[aoff[mt] + 8 * LDA + kk + tq]);
                af[mt][2] = f2tf(A[aoff[mt] + kk + tq + 4]);
                af[mt][3] = f2tf(A[aoff[mt] + 8 * LDA + kk + tq + 4]);
            }
#pragma unroll
            for (int nt = 0; nt < 4; nt++) {
                if (BNK) {
                    bf[nt][0] = f2tf(B[boff[nt] + kk + tq]);
                    bf[nt][1] = f2tf(B[boff[nt] + kk + tq + 4]);
                } else {
                    bf[nt][0] = f2tf(B[(kk + tq) * LDBK + boff[nt]]);
                    bf[nt][1] = f2tf(B[(kk + tq + 4) * LDBK + boff[nt]]);
                }
            }
#pragma unroll
            for (int mt = 0; mt < 4; mt++)
#pragma unroll
                for (int nt = 0; nt < 4; nt++)
                    mma8(acc[mt][nt], af[mt], bf[nt]);
        }
    }

    // ---- epilogue ----
#pragma unroll
    for (int mt = 0; mt < 4; mt++) {
#pragma unroll
        for (int nt = 0; nt < 4; nt++) {
#pragma unroll
            for (int r = 0; r < 4; r++) {
                int row = wm * 64 + mt * 16 + gq + ((r & 2) ? 8 : 0);
                int col = wn * 32 + nt * 8 + tq * 2 + (r & 1);
                int gm = m0 + row;
                if (EXPERT && gm >= cnt) continue;
                if (ATOMIC) {
                    atomicAdd(&C[(size_t)s_tok[row] * ldc + n0 + col],
                              acc[mt][nt][r] * s_w[row]);
                } else {
                    float* dst = C + (EXPERT ? (size_t)e * sC : 0);
                    dst[(size_t)gm * ldc + n0 + col] = acc[mt][nt][r];
                }
            }
        }
    }
}

// ================= router logits: 3xTF32 (near-fp32) =================
#define RTH 128
__global__ __launch_bounds__(RTH) void k_router_gemm(const float* __restrict__ A,
                                                     const float* __restrict__ B,
                                                     float* __restrict__ C) {
    __shared__ float As[16][64 + 4];
    __shared__ float Bsm[16][64 + 4];
    int tid = threadIdx.x;
    int warp = tid >> 5, lane = tid & 31;
    int wm = warp >> 1, wn = warp & 1, gq = lane >> 2, tq = lane & 3;
    int m0 = blockIdx.y * 64;

    const float* Ab = A + (size_t)m0 * HDIM;
    const float* Bb = B;

    float acc[2][4][4];
#pragma unroll
    for (int mt = 0; mt < 2; mt++)
#pragma unroll
        for (int nt = 0; nt < 4; nt++)
#pragma unroll
            for (int r = 0; r < 4; r++) acc[mt][nt][r] = 0.0f;

    for (int k0 = 0; k0 < HDIM; k0 += 16) {
        __syncthreads();
#pragma unroll
        for (int j = 0; j < 2; j++) {
            int it = tid + j * RTH;
            int r = it >> 2, c4 = it & 3;
            float4 va = *(const float4*)(Ab + (size_t)r * HDIM + k0 + c4 * 4);
            As[c4 * 4 + 0][r] = va.x; As[c4 * 4 + 1][r] = va.y;
            As[c4 * 4 + 2][r] = va.z; As[c4 * 4 + 3][r] = va.w;
            float4 vb = *(const float4*)(Bb + (size_t)r * HDIM + k0 + c4 * 4);
            Bsm[c4 * 4 + 0][r] = vb.x; Bsm[c4 * 4 + 1][r] = vb.y;
            Bsm[c4 * 4 + 2][r] = vb.z; Bsm[c4 * 4 + 3][r] = vb.w;
        }
        __syncthreads();
#pragma unroll
        for (int kk = 0; kk < 16; kk += 8) {
            float af[2][4], bfv[4][2];
#pragma unroll
            for (int mt = 0; mt < 2; mt++) {
                int rb = wm * 32 + mt * 16;
                af[mt][0] = As[kk + tq    ][rb + gq    ];
                af[mt][1] = As[kk + tq    ][rb + gq + 8];
                af[mt][2] = As[kk + tq + 4][rb + gq    ];
                af[mt][3] = As[kk + tq + 4][rb + gq + 8];
            }
#pragma unroll
            for (int nt = 0; nt < 4; nt++) {
                int cb = wn * 32 + nt * 8 + gq;
                bfv[nt][0] = Bsm[kk + tq    ][cb];
                bfv[nt][1] = Bsm[kk + tq + 4][cb];
            }
            unsigned ah[2][4], al[2][4], bh[4][2], bl[4][2];
#pragma unroll
            for (int mt = 0; mt < 2; mt++)
#pragma unroll
                for (int i = 0; i < 4; i++) {
                    ah[mt][i] = f2tf(af[mt][i]);
                    al[mt][i] = f2tf(af[mt][i] - __uint_as_float(ah[mt][i]));
                }
#pragma unroll
            for (int nt = 0; nt < 4; nt++)
#pragma unroll
                for (int i = 0; i < 2; i++) {
                    bh[nt][i] = f2tf(bfv[nt][i]);
                    bl[nt][i] = f2tf(bfv[nt][i] - __uint_as_float(bh[nt][i]));
                }
#pragma unroll
            for (int mt = 0; mt < 2; mt++)
#pragma unroll
                for (int nt = 0; nt < 4; nt++) {
                    mma8(acc[mt][nt], al[mt], bh[nt]);
                    mma8(acc[mt][nt], ah[mt], bl[nt]);
                    mma8(acc[mt][nt], ah[mt], bh[nt]);
                }
        }
    }
#pragma unroll
    for (int mt = 0; mt < 2; mt++)
#pragma unroll
        for (int nt = 0; nt < 4; nt++)
#pragma unroll
            for (int r = 0; r < 4; r++) {
                int row = wm * 32 + mt * 16 + gq + ((r & 2) ? 8 : 0);
                int col = wn * 32 + nt * 8 + tq * 2 + (r & 1);
                C[(size_t)(m0 + row) * NEXP + col] = acc[mt][nt][r];
            }
}

// ================= router softmax + top-6 + dispatch =================
__global__ void k_init() {
    if (threadIdx.x < NEXP) g_counts[threadIdx.x] = 0;
}

__global__ void k_router() {
    int warp = threadIdx.x >> 5, lane = threadIdx.x & 31;
    int t = blockIdx.x * 8 + warp;
    float v0 = g_logits[t * NEXP + lane];
    float v1 = g_logits[t * NEXP + 32 + lane];
    float m = fmaxf(v0, v1);
#pragma unroll
    for (int s = 16; s > 0; s >>= 1) m = fmaxf(m, __shfl_xor_sync(0xffffffffu, m, s));
    float e0 = expf(v0 - m), e1 = expf(v1 - m);
    float sum = e0 + e1;
#pragma unroll
    for (int s = 16; s > 0; s >>= 1) sum += __shfl_xor_sync(0xffffffffu, sum, s);
    float inv = 1.0f / sum;
    float p0 = e0 * inv, p1 = e1 * inv;

#pragma unroll
    for (int k = 0; k < TOPK; k++) {
        float bv; int bi;
        if (p0 >= p1) { bv = p0; bi = lane; } else { bv = p1; bi = lane + 32; }
#pragma unroll
        for (int s = 16; s > 0; s >>= 1) {
            float ov = __shfl_xor_sync(0xffffffffu, bv, s);
            int   oi = __shfl_xor_sync(0xffffffffu, bi, s);
            if (ov > bv || (ov == bv && oi < bi)) { bv = ov; bi = oi; }
        }
        if (lane == 0) {
            int pos = atomicAdd(&g_counts[bi], 1);
            if (pos < CAP) {
                g_buf_tok[bi * CAP + pos] = t;
                g_buf_w[bi * CAP + pos] = bv;
            }
        }
        if (bi < 32) { if (lane == bi) p0 = -1.0f; }
        else         { if (lane == bi - 32) p1 = -1.0f; }
    }
}

// ================= SiLU epilogues =================
__global__ void k_silu_shared() {
    size_t i = (size_t)blockIdx.x * blockDim.x + threadIdx.x;
    float4 g = ((const float4*)g_shg)[i];
    float4 u = ((const float4*)g_shu)[i];
    float4 o;
    o.x = silu_f(g.x) * u.x; o.y = silu_f(g.y) * u.y;
    o.z = silu_f(g.z) * u.z; o.w = silu_f(g.w) * u.w;
    ((float4*)g_shid)[i] = o;
}

__global__ void k_silu_routed() {   // <<<NEXP*CAP, IDIM/4>>>
    int row = blockIdx.x;           // e*CAP + c
    int c4 = threadIdx.x;           // 0..191
    int e = row >> 9, c = row & (CAP - 1);
    float4 o = make_float4(0.f, 0.f, 0.f, 0.f);
    if (c < g_counts[e]) {
        const float* gu = g_gu + (size_t)row * TWOI;
        float4 g = *(const float4*)(gu + c4 * 4);
        float4 u = *(const float4*)(gu + IDIM + c4 * 4);
        o.x = silu_f(g.x) * u.x; o.y = silu_f(g.y) * u.y;
        o.z = silu_f(g.z) * u.z; o.w = silu_f(g.w) * u.w;
    }
    ((float4*)g_hid)[(size_t)row * (IDIM / 4) + c4] = o;
}

// ================= launch =================
extern "C" void kernel_launch(void* const* d_in, const int* in_sizes, int n_in,
                              void* d_out, int out_size) {
    const float* x   = (const float*)d_in[0];
    const float* gw  = (const float*)d_in[1];
    const float* gup = (const float*)d_in[2];
    const float* dwn = (const float*)d_in[3];
    const float* sgw = (const float*)d_in[4];
    const float* suw = (const float*)d_in[5];
    const float* sdw = (const float*)d_in[6];
    float* out = (float*)d_out;

    float *p_logits, *p_gu, *p_hid, *p_shg, *p_shu, *p_shid;
    cudaGetSymbolAddress((void**)&p_logits, g_logits);
    cudaGetSymbolAddress((void**)&p_gu,   g_gu);
    cudaGetSymbolAddress((void**)&p_hid,  g_hid);
    cudaGetSymbolAddress((void**)&p_shg,  g_shg);
    cudaGetSymbolAddress((void**)&p_shu,  g_shu);
    cudaGetSymbolAddress((void**)&p_shid, g_shid);

    cudaFuncSetAttribute(k_gemm<1,0,0,0>, cudaFuncAttributeMaxDynamicSharedMemorySize, SMEM_DYN);
    cudaFuncSetAttribute(k_gemm<0,1,1,0>, cudaFuncAttributeMaxDynamicSharedMemorySize, SMEM_DYN);
    cudaFuncSetAttribute(k_gemm<0,1,0,1>, cudaFuncAttributeMaxDynamicSharedMemorySize, SMEM_DYN);

    k_init<<<1, 64>>>();
    // router: near-fp32 logits so top-k matches reference exactly
    k_router_gemm<<<dim3(1, NTOK / 64), RTH>>>(x, gw, p_logits);
    k_router<<<NTOK / 8, 256>>>();

    // shared experts (weights [N,K]): g, u, silu, then down -> out (plain store covers out)
    k_gemm<1,0,0,0><<<dim3(SIDIM / BN, NTOK / BM), NTH, SMEM_DYN>>>(
        x, sgw, p_shg, HDIM, 0, SIDIM, 0, 0, 0);
    k_gemm<1,0,0,0><<<dim3(SIDIM / BN, NTOK / BM), NTH, SMEM_DYN>>>(
        x, suw, p_shu, HDIM, 0, SIDIM, 0, 0, 0);
    k_silu_shared<<<(NTOK * SIDIM / 4) / 256, 256>>>();
    k_gemm<1,0,0,0><<<dim3(HDIM / BN, NTOK / BM), NTH, SMEM_DYN>>>(
        p_shid, sdw, out, SIDIM, 0, HDIM, 0, 0, 0);

    // routed experts: gate_up (gathered A, weights [K,N]), silu, down (atomic scatter-add)
    k_gemm<0,1,1,0><<<dim3(TWOI / BN, CAP / BM, NEXP), NTH, SMEM_DYN>>>(
        x, gup, p_gu, HDIM, TWOI, TWOI, 0, (long)HDIM * TWOI, (long)CAP * TWOI);
    k_silu_routed<<<NEXP * CAP, IDIM / 4>>>();
    k_gemm<0,1,0,1><<<dim3(HDIM / BN, CAP / BM, NEXP), NTH, SMEM_DYN>>>(
        p_hid, dwn, out, IDIM, HDIM, HDIM, (long)CAP * IDIM, (long)IDIM * HDIM, 0);
}